// round 1
// baseline (speedup 1.0000x reference)
#include <cuda_runtime.h>

// ---------------- problem constants ----------------
#define INS   224
#define NH    220
#define NB    48400        // NH*NH
#define KL    5
#define ICH   16
#define OCH   64
#define KTOT  400          // ICH*KL*KL
#define NBANDS 110         // 220 rows / 2 rows per band
#define PIX_PER_BAND 440   // 2*220
#define CHUNK 40           // pixels per smem chunk (11 chunks per band)

// output packing: [out | Wfinal | exp_new]
#define OUT_OFF_W   (OCH*NB)          // 3097600
#define OUT_OFF_EXP (OUT_OFF_W + OCH*KTOT)  // 3123200

// ---------------- scratch (device globals; no allocation) ----------------
__device__ float g_y[NB * OCH];                       // inhibited output, (pixel, oc)
__device__ float g_Cpart[NBANDS * OCH * KTOT];        // partial y^T @ xf
__device__ float g_ytypart[NBANDS * OCH * OCH];       // partial y^T @ y
__device__ float g_colpart[NBANDS * OCH];             // partial column sums of y
__device__ float g_Cfin[OCH * KTOT];
__device__ float g_ytyF[OCH * OCH];
__device__ float g_colF[OCH];
__device__ float g_gfp[OCH];

// ======================================================================
// K1: conv + inhibition. Block = 128 threads, covers 8x16 pixel tile,
// each thread: 4 pixels (consecutive j) x 16 output channels.
// grid (14, 28)
// ======================================================================
__global__ void __launch_bounds__(128, 4)
k_conv(const float* __restrict__ x, const float* __restrict__ W,
       float* __restrict__ dout)
{
    __shared__ float xs[12 * 21];     // 12 rows x (20 cols, stride 21)
    __shared__ float ws[25 * 64];     // W slice for current ic: [kk][oc]
    __shared__ float mtmp[4][128];    // per-pixel channel-group maxima

    const int tid = threadIdx.x;
    const int ocg = tid & 3;          // 4 channel groups of 16
    const int pg  = tid >> 2;         // 32 pixel groups of 4
    const int li  = pg >> 2;          // local row 0..7
    const int lj0 = (pg & 3) * 4;     // local col start 0,4,8,12
    const int i0  = blockIdx.y * 8;
    const int j0  = blockIdx.x * 16;
    const int oc0 = ocg * 16;

    float acc[4][16];
#pragma unroll
    for (int q = 0; q < 4; q++)
#pragma unroll
        for (int o = 0; o < 16; o++) acc[q][o] = 0.f;

    const int xbase = li * 21 + lj0;

    for (int ic = 0; ic < ICH; ic++) {
        __syncthreads();
        // load x halo tile for this ic (rows i0..i0+11, cols j0..j0+20, clamped)
        for (int lin = tid; lin < 12 * 21; lin += 128) {
            int r = lin / 21, c = lin - r * 21;
            int gi = min(i0 + r, INS - 1);
            int gj = min(j0 + c, INS - 1);
            xs[lin] = x[ic * (INS * INS) + gi * INS + gj];
        }
        // load W slice transposed: ws[kk*64+oc] = W[oc][ic*25+kk]
        for (int lin = tid; lin < 25 * 64; lin += 128) {
            int oc = lin & 63, kk = lin >> 6;
            ws[lin] = W[oc * KTOT + ic * 25 + kk];
        }
        __syncthreads();

#pragma unroll 1
        for (int ki = 0; ki < 5; ki++) {
#pragma unroll
            for (int kj = 0; kj < 5; kj++) {
                float xv[4];
#pragma unroll
                for (int q = 0; q < 4; q++)
                    xv[q] = xs[xbase + ki * 21 + kj + q];
                const float4* wp = (const float4*)&ws[(ki * 5 + kj) * 64 + oc0];
#pragma unroll
                for (int w4 = 0; w4 < 4; w4++) {
                    float4 w = wp[w4];
#pragma unroll
                    for (int q = 0; q < 4; q++) {
                        acc[q][w4 * 4 + 0] += xv[q] * w.x;
                        acc[q][w4 * 4 + 1] += xv[q] * w.y;
                        acc[q][w4 * 4 + 2] += xv[q] * w.z;
                        acc[q][w4 * 4 + 3] += xv[q] * w.w;
                    }
                }
            }
        }
    }

    // per-pixel max over all 64 channels (relu'd)
#pragma unroll
    for (int q = 0; q < 4; q++) {
        float m = 0.f;
#pragma unroll
        for (int o = 0; o < 16; o++) m = fmaxf(m, acc[q][o]);
        mtmp[ocg][pg * 4 + q] = m;
    }
    __syncthreads();

    const int i = i0 + li;
    const int j = j0 + lj0;

#pragma unroll
    for (int q = 0; q < 4; q++) {
        float m = fmaxf(fmaxf(mtmp[0][pg * 4 + q], mtmp[1][pg * 4 + q]),
                        fmaxf(mtmp[2][pg * 4 + q], mtmp[3][pg * 4 + q]));
        float inv = 1.f / (m + 1e-9f);
#pragma unroll
        for (int o = 0; o < 16; o++) {
            float v = fmaxf(acc[q][o], 0.f) * inv;
            float v2 = v * v;
            acc[q][o] = v2 * v2 * v;   // v^5
        }
    }

    if (i < NH && j < NH) {
        // NCHW output region
#pragma unroll
        for (int o = 0; o < 16; o++) {
            float4 v = make_float4(acc[0][o], acc[1][o], acc[2][o], acc[3][o]);
            *(float4*)&dout[(oc0 + o) * NB + i * NH + j] = v;
        }
        // y scratch: (pixel, oc)
        int p = i * NH + j;
#pragma unroll
        for (int q = 0; q < 4; q++) {
#pragma unroll
            for (int w4 = 0; w4 < 4; w4++) {
                float4 v = make_float4(acc[q][w4 * 4 + 0], acc[q][w4 * 4 + 1],
                                       acc[q][w4 * 4 + 2], acc[q][w4 * 4 + 3]);
                *(float4*)&g_y[(p + q) * OCH + oc0 + w4 * 4] = v;
            }
        }
    }
}

// ======================================================================
// K2: partial y^T y (64x64) + column sums, one block per 2-row band.
// grid 110, block 256. thread: 1 row-a x 16 cols-b.
// ======================================================================
__global__ void k_yty()
{
    __shared__ float ys[CHUNK * OCH];
    const int tid = threadIdx.x;
    const int band = blockIdx.x;
    const int a = tid >> 2;
    const int bq = (tid & 3) << 4;

    float acc[16];
#pragma unroll
    for (int o = 0; o < 16; o++) acc[o] = 0.f;
    float csum = 0.f;

    for (int ch = 0; ch < PIX_PER_BAND / CHUNK; ch++) {
        __syncthreads();
        int pbase = band * PIX_PER_BAND + ch * CHUNK;
        for (int lin = tid; lin < CHUNK * OCH; lin += 256)
            ys[lin] = g_y[pbase * OCH + lin];
        __syncthreads();

        for (int p = 0; p < CHUNK; p++) {
            float ya = ys[p * OCH + a];
            const float4* yb = (const float4*)&ys[p * OCH + bq];
#pragma unroll
            for (int w4 = 0; w4 < 4; w4++) {
                float4 v = yb[w4];
                acc[w4 * 4 + 0] += ya * v.x;
                acc[w4 * 4 + 1] += ya * v.y;
                acc[w4 * 4 + 2] += ya * v.z;
                acc[w4 * 4 + 3] += ya * v.w;
            }
            if ((tid & 3) == 0) csum += ya;
        }
    }

#pragma unroll
    for (int w4 = 0; w4 < 4; w4++) {
        float4 v = make_float4(acc[w4 * 4 + 0], acc[w4 * 4 + 1],
                               acc[w4 * 4 + 2], acc[w4 * 4 + 3]);
        *(float4*)&g_ytypart[band * (OCH * OCH) + a * OCH + bq + w4 * 4] = v;
    }
    if ((tid & 3) == 0) g_colpart[band * OCH + a] = csum;
}

// ======================================================================
// K3: partial y^T @ xf. grid (5 k-tiles of 80, 110 bands), block 128.
// thread: 8 oc x 5 k register tile.
// ======================================================================
__global__ void __launch_bounds__(128)
k_ytxf(const float* __restrict__ x)
{
    __shared__ float ys[CHUNK * OCH];    // 2560
    __shared__ float xsf[CHUNK * 80];    // 3200
    const int tid = threadIdx.x;
    const int kt = blockIdx.x;
    const int band = blockIdx.y;
    const int ty = tid >> 4;             // 0..7 -> oc0 = ty*8
    const int tx = tid & 15;             // 0..15 -> kk0 = tx*5
    const int oc0 = ty * 8;
    const int kk0 = tx * 5;

    float acc[8][5];
#pragma unroll
    for (int r = 0; r < 8; r++)
#pragma unroll
        for (int u = 0; u < 5; u++) acc[r][u] = 0.f;

    for (int ch = 0; ch < PIX_PER_BAND / CHUNK; ch++) {
        __syncthreads();
        int pbase = band * PIX_PER_BAND + ch * CHUNK;
        for (int lin = tid; lin < CHUNK * OCH; lin += 128)
            ys[lin] = g_y[pbase * OCH + lin];
        for (int lin = tid; lin < CHUNK * 80; lin += 128) {
            int p = lin / 80, kk = lin - p * 80;
            int pc = pbase + p;
            int i = pc / NH, j = pc - i * NH;
            int k = kt * 80 + kk;
            int ic = k / 25, rem = k - ic * 25;
            int ki = rem / 5, kj = rem - ki * 5;
            xsf[lin] = x[ic * (INS * INS) + (i + ki) * INS + (j + kj)];
        }
        __syncthreads();

        for (int p = 0; p < CHUNK; p++) {
            float4 y4a = *(const float4*)&ys[p * OCH + oc0];
            float4 y4b = *(const float4*)&ys[p * OCH + oc0 + 4];
            float xv[5];
#pragma unroll
            for (int u = 0; u < 5; u++) xv[u] = xsf[p * 80 + kk0 + u];
#pragma unroll
            for (int u = 0; u < 5; u++) {
                acc[0][u] += y4a.x * xv[u];
                acc[1][u] += y4a.y * xv[u];
                acc[2][u] += y4a.z * xv[u];
                acc[3][u] += y4a.w * xv[u];
                acc[4][u] += y4b.x * xv[u];
                acc[5][u] += y4b.y * xv[u];
                acc[6][u] += y4b.z * xv[u];
                acc[7][u] += y4b.w * xv[u];
            }
        }
    }

    float* Cp = &g_Cpart[band * (OCH * KTOT)];
#pragma unroll
    for (int r = 0; r < 8; r++)
#pragma unroll
        for (int u = 0; u < 5; u++)
            Cp[(oc0 + r) * KTOT + kt * 80 + kk0 + u] = acc[r][u];
}

// ======================================================================
// K4: deterministic tree-reduce of band partials.
// ======================================================================
__global__ void k_reduce()
{
    int idx = blockIdx.x * 256 + threadIdx.x;
    if (idx < OCH * KTOT) {
        float s = 0.f;
        for (int b = 0; b < NBANDS; b++) s += g_Cpart[b * (OCH * KTOT) + idx];
        g_Cfin[idx] = s;
    } else if (idx < OCH * KTOT + OCH * OCH) {
        int i = idx - OCH * KTOT;
        float s = 0.f;
        for (int b = 0; b < NBANDS; b++) s += g_ytypart[b * (OCH * OCH) + i];
        g_ytyF[i] = s;
    } else if (idx < OCH * KTOT + OCH * OCH + OCH) {
        int i = idx - (OCH * KTOT + OCH * OCH);
        float s = 0.f;
        for (int b = 0; b < NBANDS; b++) s += g_colpart[b * OCH + i];
        g_colF[i] = s;
    }
}

// ======================================================================
// K5: exp_new / gfp. 1 block, 64 threads.
// ======================================================================
__global__ void k_exp(const float* __restrict__ exp_avg, float* __restrict__ dout)
{
    __shared__ float sh[OCH];
    int t = threadIdx.x;
    float mean_y = g_colF[t] * (1.0f / (float)NB);
    float en = 0.99f * exp_avg[t] + (1.0f - 0.99f) * mean_y;
    sh[t] = en;
    __syncthreads();
    float s = 0.f;
    for (int i = 0; i < OCH; i++) s += sh[i];   // deterministic, identical on all threads
    float A = en / (s * (1.0f / (float)OCH));
    float gfp = 0.01f * tanhf(-0.01f * (A - 1.0f)) + 1.0f;
    g_gfp[t] = gfp;
    dout[OUT_OFF_EXP + t] = en;
}

// ======================================================================
// K6: weight update. Wfinal = relu(Wf + LR/NB*(C - yty@Wf)) * gfp[oc]
// (the negative branch is dead: relu output >= 0)
// ======================================================================
__global__ void k_wupd(const float* __restrict__ W, float* __restrict__ dout)
{
    int idx = blockIdx.x * 256 + threadIdx.x;
    if (idx >= OCH * KTOT) return;
    int oc = idx / KTOT;
    int k = idx - oc * KTOT;
    float dot = 0.f;
#pragma unroll 8
    for (int b = 0; b < OCH; b++)
        dot += g_ytyF[oc * OCH + b] * W[b * KTOT + k];
    const float LRN = (float)(0.005 / 48400.0);
    float d = LRN * (g_Cfin[idx] - dot);
    float wn = fmaxf(W[idx] + d, 0.f);
    dout[OUT_OFF_W + idx] = wn * g_gfp[oc];
}

// ======================================================================
extern "C" void kernel_launch(void* const* d_in, const int* in_sizes, int n_in,
                              void* d_out, int out_size)
{
    const float* x  = (const float*)d_in[0];   // (1,16,224,224)
    const float* W  = (const float*)d_in[1];   // (64,16,5,5)
    const float* ea = (const float*)d_in[2];   // (64,)
    float* dout = (float*)d_out;

    dim3 g1(14, 28);
    k_conv<<<g1, 128>>>(x, W, dout);
    k_yty<<<NBANDS, 256>>>();
    dim3 g3(5, NBANDS);
    k_ytxf<<<g3, 128>>>(x);
    k_reduce<<<(OCH * KTOT + OCH * OCH + OCH + 255) / 256, 256>>>();
    k_exp<<<1, OCH>>>(ea, dout);
    k_wupd<<<(OCH * KTOT) / 256, 256>>>(W, dout);
}

// round 2
// speedup vs baseline: 1.1307x; 1.1307x over previous
#include <cuda_runtime.h>

typedef unsigned long long ull;

// ---------------- problem constants ----------------
#define INS   224
#define NH    220
#define NB    48400        // NH*NH
#define ICH   16
#define OCH   64
#define KTOT  400          // ICH*5*5
#define NBANDS 110         // 220 rows / 2 rows per band
#define PIX_PER_BAND 440
#define CHUNK 40

#define OUT_OFF_W   (OCH*NB)                 // 3097600
#define OUT_OFF_EXP (OUT_OFF_W + OCH*KTOT)   // 3123200

// ---------------- scratch ----------------
__device__ float g_Wt[KTOT * OCH];                 // [ic][25][oc]
__device__ float g_y[NB * OCH];                    // (pixel, oc)
__device__ float g_Cpart[NBANDS * OCH * KTOT];
__device__ float g_ytypart[NBANDS * OCH * OCH];
__device__ float g_colpart[NBANDS * OCH];
__device__ float g_Cred[10 * OCH * KTOT];
__device__ float g_ytyred[10 * OCH * OCH];
__device__ float g_Cfin[OCH * KTOT];
__device__ float g_ytyF[OCH * OCH];
__device__ float g_gfp[OCH];

// ---------------- f32x2 helpers ----------------
__device__ __forceinline__ ull pack2(float lo, float hi) {
    ull r; asm("mov.b64 %0, {%1,%2};" : "=l"(r) : "f"(lo), "f"(hi)); return r;
}
__device__ __forceinline__ float2 unpack2(ull v) {
    float2 f; asm("mov.b64 {%0,%1}, %2;" : "=f"(f.x), "=f"(f.y) : "l"(v)); return f;
}
#define FMA2(acc, a, b) asm("fma.rn.f32x2 %0, %1, %2, %0;" : "+l"(acc) : "l"(a), "l"(b))

// ======================================================================
// K0: transpose W -> g_Wt[ic*1600 + kk*64 + oc]
// ======================================================================
__global__ void k_prep(const float* __restrict__ W)
{
    int idx = blockIdx.x * 256 + threadIdx.x;
    if (idx >= KTOT * OCH) return;
    int oc = idx & 63;
    int t  = idx >> 6;          // ic*25 + kk
    int ic = t / 25, kk = t - ic * 25;
    g_Wt[idx] = W[oc * KTOT + ic * 25 + kk];
}

// ======================================================================
// K1: conv + inhibition, FFMA2. 128 thr, 8x16 px tile, grid (14,28).
// Thread: 4 px x 8 oc-pairs (16 oc).
// ======================================================================
__global__ void __launch_bounds__(128)
k_conv(const float* __restrict__ x, float* __restrict__ dout)
{
    __shared__ float xs[12 * 21];
    __shared__ float ws[25 * 64];
    __shared__ float mtmp[4][128];

    const int tid = threadIdx.x;
    const int ocg = tid & 3;
    const int pg  = tid >> 2;
    const int li  = pg >> 2;
    const int lj0 = (pg & 3) * 4;
    const int i0  = blockIdx.y * 8;
    const int j0  = blockIdx.x * 16;
    const int oc0 = ocg * 16;

    ull acc2[4][8];
#pragma unroll
    for (int q = 0; q < 4; q++)
#pragma unroll
        for (int w = 0; w < 8; w++) acc2[q][w] = 0ULL;

    const int xbase = li * 21 + lj0;

    for (int ic = 0; ic < ICH; ic++) {
        __syncthreads();
        for (int lin = tid; lin < 12 * 21; lin += 128) {
            int r = lin / 21, c = lin - r * 21;
            int gi = min(i0 + r, INS - 1);
            int gj = min(j0 + c, INS - 1);
            xs[lin] = x[ic * (INS * INS) + gi * INS + gj];
        }
        const float4* wsrc = (const float4*)(g_Wt + ic * 1600);
        for (int v = tid; v < 400; v += 128)
            ((float4*)ws)[v] = wsrc[v];
        __syncthreads();

#pragma unroll 1
        for (int ki = 0; ki < 5; ki++) {
#pragma unroll
            for (int kj = 0; kj < 5; kj++) {
                ull xv2[4];
#pragma unroll
                for (int q = 0; q < 4; q++) {
                    float v = xs[xbase + ki * 21 + kj + q];
                    xv2[q] = pack2(v, v);
                }
                const ulonglong2* wp =
                    (const ulonglong2*)&ws[(ki * 5 + kj) * 64 + oc0];
#pragma unroll
                for (int w = 0; w < 4; w++) {
                    ulonglong2 ww = wp[w];
#pragma unroll
                    for (int q = 0; q < 4; q++) {
                        FMA2(acc2[q][2 * w],     xv2[q], ww.x);
                        FMA2(acc2[q][2 * w + 1], xv2[q], ww.y);
                    }
                }
            }
        }
    }

    // per-pixel max over this thread's 16 oc
#pragma unroll
    for (int q = 0; q < 4; q++) {
        float m = 0.f;
#pragma unroll
        for (int w = 0; w < 8; w++) {
            float2 f = unpack2(acc2[q][w]);
            m = fmaxf(m, fmaxf(f.x, f.y));
        }
        mtmp[ocg][pg * 4 + q] = m;
    }
    __syncthreads();

    const int i = i0 + li;
    const int j = j0 + lj0;
    float minv[4];
#pragma unroll
    for (int q = 0; q < 4; q++) {
        float m = fmaxf(fmaxf(mtmp[0][pg * 4 + q], mtmp[1][pg * 4 + q]),
                        fmaxf(mtmp[2][pg * 4 + q], mtmp[3][pg * 4 + q]));
        minv[q] = 1.f / (m + 1e-9f);
    }

    if (i < NH && j < NH) {
        const int p = i * NH + j;
#pragma unroll
        for (int w = 0; w < 8; w += 2) {   // 4 oc at a time
            float vals[4][4];
#pragma unroll
            for (int q = 0; q < 4; q++) {
                float2 fa = unpack2(acc2[q][w]);
                float2 fb = unpack2(acc2[q][w + 1]);
                vals[q][0] = fa.x; vals[q][1] = fa.y;
                vals[q][2] = fb.x; vals[q][3] = fb.y;
            }
#pragma unroll
            for (int q = 0; q < 4; q++)
#pragma unroll
                for (int o = 0; o < 4; o++) {
                    float v = fmaxf(vals[q][o], 0.f) * minv[q];
                    float v2 = v * v;
                    vals[q][o] = v2 * v2 * v;
                }
            int obase = oc0 + 2 * w;
#pragma unroll
            for (int o = 0; o < 4; o++)
                *(float4*)&dout[(obase + o) * NB + p] =
                    make_float4(vals[0][o], vals[1][o], vals[2][o], vals[3][o]);
#pragma unroll
            for (int q = 0; q < 4; q++)
                *(float4*)&g_y[(p + q) * OCH + obase] =
                    make_float4(vals[q][0], vals[q][1], vals[q][2], vals[q][3]);
        }
    }
}

// ======================================================================
// K2: fused y^T@xf (kt 0..4) and y^T@y + colsums (kt==5).
// grid (6, 110), 128 threads.
// ======================================================================
__global__ void __launch_bounds__(128)
k_hebb(const float* __restrict__ x)
{
    __shared__ float ys[CHUNK * OCH];    // 2560
    __shared__ float xsf[CHUNK * 80];    // 3200
    __shared__ int offs[80];
    __shared__ int bases[PIX_PER_BAND];

    const int tid = threadIdx.x;
    const int kt = blockIdx.x;
    const int band = blockIdx.y;

    if (kt < 5) {
        // ---------- y^T @ xf ----------
        if (tid < 80) {
            int k = kt * 80 + tid;
            int ic = k / 25, rem = k - ic * 25;
            int ki = rem / 5, kj = rem - ki * 5;
            offs[tid] = ic * (INS * INS) + ki * INS + kj;
        }
        for (int v = tid; v < PIX_PER_BAND; v += 128) {
            int pc = band * PIX_PER_BAND + v;
            int i = pc / NH, j = pc - i * NH;
            bases[v] = i * INS + j;
        }
        __syncthreads();

        const int ty = tid >> 4;        // 0..7 -> oc0 = ty*8
        const int tx = tid & 15;        // 0..15 -> kk0 = tx*5
        const int oc0 = ty * 8;
        const int kk0 = tx * 5;

        ull acc2[4][5];
#pragma unroll
        for (int r = 0; r < 4; r++)
#pragma unroll
            for (int u = 0; u < 5; u++) acc2[r][u] = 0ULL;

        for (int ch = 0; ch < PIX_PER_BAND / CHUNK; ch++) {
            int pbase = band * PIX_PER_BAND + ch * CHUNK;
            const float4* ysrc = (const float4*)(g_y + pbase * OCH);
            for (int v = tid; v < 640; v += 128)
                ((float4*)ys)[v] = ysrc[v];
            for (int idx = tid; idx < CHUNK * 80; idx += 128) {
                int p = idx / 80, kk = idx - p * 80;
                xsf[idx] = x[offs[kk] + bases[ch * CHUNK + p]];
            }
            __syncthreads();

            for (int p = 0; p < CHUNK; p++) {
                const ulonglong2* yp = (const ulonglong2*)&ys[p * OCH + oc0];
                ulonglong2 ya = yp[0], yb = yp[1];
                ull yr[4] = {ya.x, ya.y, yb.x, yb.y};
                ull xv2[5];
#pragma unroll
                for (int u = 0; u < 5; u++) {
                    float v = xsf[p * 80 + kk0 + u];
                    xv2[u] = pack2(v, v);
                }
#pragma unroll
                for (int u = 0; u < 5; u++)
#pragma unroll
                    for (int r = 0; r < 4; r++)
                        FMA2(acc2[r][u], yr[r], xv2[u]);
            }
            __syncthreads();
        }

        float* Cp = &g_Cpart[band * (OCH * KTOT)];
#pragma unroll
        for (int r = 0; r < 4; r++)
#pragma unroll
            for (int u = 0; u < 5; u++) {
                float2 f = unpack2(acc2[r][u]);
                int col = kt * 80 + kk0 + u;
                Cp[(oc0 + 2 * r) * KTOT + col] = f.x;
                Cp[(oc0 + 2 * r + 1) * KTOT + col] = f.y;
            }
    } else {
        // ---------- y^T @ y + column sums ----------
        const int a = tid >> 1;              // row 0..63
        const int bq = (tid & 1) * 32;       // col half
        ull acc2[16];
#pragma unroll
        for (int w = 0; w < 16; w++) acc2[w] = 0ULL;
        float csum = 0.f;

        for (int ch = 0; ch < PIX_PER_BAND / CHUNK; ch++) {
            int pbase = band * PIX_PER_BAND + ch * CHUNK;
            const float4* ysrc = (const float4*)(g_y + pbase * OCH);
            for (int v = tid; v < 640; v += 128)
                ((float4*)ys)[v] = ysrc[v];
            __syncthreads();

            for (int p = 0; p < CHUNK; p++) {
                float ya = ys[p * OCH + a];
                ull ya2 = pack2(ya, ya);
                const ulonglong2* yb = (const ulonglong2*)&ys[p * OCH + bq];
#pragma unroll
                for (int w = 0; w < 8; w++) {
                    ulonglong2 v = yb[w];
                    FMA2(acc2[2 * w],     ya2, v.x);
                    FMA2(acc2[2 * w + 1], ya2, v.y);
                }
                if ((tid & 1) == 0) csum += ya;
            }
            __syncthreads();
        }

        float* Yp = &g_ytypart[band * (OCH * OCH) + a * OCH + bq];
#pragma unroll
        for (int w = 0; w < 16; w++) {
            float2 f = unpack2(acc2[w]);
            Yp[2 * w] = f.x;
            Yp[2 * w + 1] = f.y;
        }
        if ((tid & 1) == 0) g_colpart[band * OCH + a] = csum;
    }
}

// ======================================================================
// K3: reduction stage 1: 110 bands -> 10 groups (float4 lanes).
// grid (29, 10), 256 threads.
// ======================================================================
__global__ void k_reduce1()
{
    int e = blockIdx.x * 256 + threadIdx.x;
    int g = blockIdx.y;
    if (e < 6400) {
        const float4* P = (const float4*)g_Cpart;
        float4 s = make_float4(0.f, 0.f, 0.f, 0.f);
#pragma unroll
        for (int b = 0; b < 11; b++) {
            float4 v = P[(g * 11 + b) * 6400 + e];
            s.x += v.x; s.y += v.y; s.z += v.z; s.w += v.w;
        }
        ((float4*)g_Cred)[g * 6400 + e] = s;
    } else if (e < 6400 + 1024) {
        int i = e - 6400;
        const float4* P = (const float4*)g_ytypart;
        float4 s = make_float4(0.f, 0.f, 0.f, 0.f);
#pragma unroll
        for (int b = 0; b < 11; b++) {
            float4 v = P[(g * 11 + b) * 1024 + i];
            s.x += v.x; s.y += v.y; s.z += v.z; s.w += v.w;
        }
        ((float4*)g_ytyred)[g * 1024 + i] = s;
    }
}

// ======================================================================
// K4: reduction stage 2 (+ exp_new / gfp in block 0).
// grid 29, 256 threads.
// ======================================================================
__global__ void k_reduce2(const float* __restrict__ exp_avg,
                          float* __restrict__ dout)
{
    int e = blockIdx.x * 256 + threadIdx.x;
    if (e < 6400) {
        const float4* P = (const float4*)g_Cred;
        float4 s = make_float4(0.f, 0.f, 0.f, 0.f);
#pragma unroll
        for (int gg = 0; gg < 10; gg++) {
            float4 v = P[gg * 6400 + e];
            s.x += v.x; s.y += v.y; s.z += v.z; s.w += v.w;
        }
        ((float4*)g_Cfin)[e] = s;
    } else if (e < 6400 + 1024) {
        int i = e - 6400;
        const float4* P = (const float4*)g_ytyred;
        float4 s = make_float4(0.f, 0.f, 0.f, 0.f);
#pragma unroll
        for (int gg = 0; gg < 10; gg++) {
            float4 v = P[gg * 1024 + i];
            s.x += v.x; s.y += v.y; s.z += v.z; s.w += v.w;
        }
        ((float4*)g_ytyF)[i] = s;
    }

    if (blockIdx.x == 0) {
        __shared__ float sh[OCH];
        int t = threadIdx.x;
        if (t < OCH) {
            float cs = 0.f;
#pragma unroll 10
            for (int b = 0; b < NBANDS; b++) cs += g_colpart[b * OCH + t];
            float en = 0.99f * exp_avg[t] + (1.0f - 0.99f) * (cs / (float)NB);
            sh[t] = en;
            dout[OUT_OFF_EXP + t] = en;
        }
        __syncthreads();
        if (t < OCH) {
            float s = 0.f;
            for (int i = 0; i < OCH; i++) s += sh[i];
            float A = sh[t] / (s * (1.0f / (float)OCH));
            g_gfp[t] = 0.01f * tanhf(-0.01f * (A - 1.0f)) + 1.0f;
        }
    }
}

// ======================================================================
// K5: weight update.
// ======================================================================
__global__ void k_wupd(const float* __restrict__ W, float* __restrict__ dout)
{
    int idx = blockIdx.x * 256 + threadIdx.x;
    if (idx >= OCH * KTOT) return;
    int oc = idx / KTOT;
    int k = idx - oc * KTOT;
    float dot = 0.f;
#pragma unroll 8
    for (int b = 0; b < OCH; b++)
        dot += g_ytyF[oc * OCH + b] * W[b * KTOT + k];
    const float LRN = (float)(0.005 / 48400.0);
    float d = LRN * (g_Cfin[idx] - dot);
    float wn = fmaxf(W[idx] + d, 0.f);
    dout[OUT_OFF_W + idx] = wn * g_gfp[oc];
}

// ======================================================================
extern "C" void kernel_launch(void* const* d_in, const int* in_sizes, int n_in,
                              void* d_out, int out_size)
{
    const float* x  = (const float*)d_in[0];
    const float* W  = (const float*)d_in[1];
    const float* ea = (const float*)d_in[2];
    float* dout = (float*)d_out;

    k_prep<<<100, 256>>>(W);
    dim3 g1(14, 28);
    k_conv<<<g1, 128>>>(x, dout);
    dim3 g2(6, NBANDS);
    k_hebb<<<g2, 128>>>(x);
    dim3 g3(29, 10);
    k_reduce1<<<g3, 256>>>();
    k_reduce2<<<29, 256>>>(ea, dout);
    k_wupd<<<100, 256>>>(W, dout);
}